// round 8
// baseline (speedup 1.0000x reference)
#include <cuda_runtime.h>

// out[b,o] = ( x @ softmax(W,axis=1)^T > 0.5 )
// BIT-REPLICATION constraints (verified: 1 flip @ rel_err 4.888245e-4):
//  - softmax: XLA row-reduction tree replica (kernel 1, DO NOT REORDER)
//  - GEMM: per-output serial ascending-k fp32 chain. x in {0,1}:
//      x=1: @p add.rn.f32x2 == fl(acc+b) == reference fl(1*w+acc)
//      x=0: predicated-off == acc unchanged == reference fl(0*w+acc)
// R8: A carried as BYTES (pre-transposed xT[k][m]) -> A smem reads are
// LDS.32 instead of LDS.128, breaking the fma/crossbar co-bind at 62%.

#define M_DIM 4096
#define N_DIM 2048
#define K_DIM 2048

__device__ float g_w[(size_t)N_DIM * K_DIM];
__device__ unsigned char g_xbT[(size_t)K_DIM * M_DIM];  // xT[k][m] as 0/1 bytes

// ---------------------------------------------------------------------------
// Kernel 0: transpose+convert x [M,K] f32 -> g_xbT [K,M] u8.
// Tile: 128 m x 32 k per block, 256 threads.
// ---------------------------------------------------------------------------
__global__ __launch_bounds__(256) void transpose_x_kernel(const float* __restrict__ x) {
    __shared__ unsigned char tb[32][144];  // 144 = 9*16 keeps 16B alignment
    const int m0 = blockIdx.y * 128;
    const int k0 = blockIdx.x * 32;
    const int tid = threadIdx.x;

#pragma unroll
    for (int it = 0; it < 4; ++it) {
        const int idx = tid + it * 256;   // 0..1023
        const int r = idx >> 3;           // 0..127 (m)
        const int c = (idx & 7) * 4;      // 0..28  (k)
        const float4 v = *(const float4*)&x[(size_t)(m0 + r) * K_DIM + k0 + c];
        tb[c + 0][r] = (v.x != 0.f);
        tb[c + 1][r] = (v.y != 0.f);
        tb[c + 2][r] = (v.z != 0.f);
        tb[c + 3][r] = (v.w != 0.f);
    }
    __syncthreads();

    const int r = tid >> 3;          // 0..31 (k)
    const int c = (tid & 7) * 16;    // 0..112 (m)
    const uint4 w = *(const uint4*)&tb[r][c];
    *(uint4*)&g_xbT[(size_t)(k0 + r) * M_DIM + m0 + c] = w;
}

// ---------------------------------------------------------------------------
// Kernel 1: XLA softmax replica (unchanged — bit-exact anchor).
// ---------------------------------------------------------------------------
__global__ __launch_bounds__(1024) void softmax_rows_kernel(const float* __restrict__ raw) {
    const int row = blockIdx.x;
    const int tid = threadIdx.x;
    const int lane = tid & 31;
    const int wid = tid >> 5;

    const float2* __restrict__ r2 =
        reinterpret_cast<const float2*>(raw + (size_t)row * K_DIM);
    float2* __restrict__ w2 = reinterpret_cast<float2*>(g_w + (size_t)row * K_DIM);

    const float2 v = r2[tid];

    __shared__ float s_part[32];
    __shared__ float s_bcast;

    float m = fmaxf(v.x, v.y);
#pragma unroll
    for (int off = 16; off > 0; off >>= 1)
        m = fmaxf(m, __shfl_down_sync(0xffffffffu, m, off));
    if (lane == 0) s_part[wid] = m;
    __syncthreads();
    if (wid == 0) {
        float t = s_part[lane];
#pragma unroll
        for (int off = 16; off > 0; off >>= 1)
            t = fmaxf(t, __shfl_down_sync(0xffffffffu, t, off));
        if (lane == 0) s_bcast = t;
    }
    __syncthreads();
    m = s_bcast;
    __syncthreads();

    const float e0 = expf(v.x - m);
    const float e1 = expf(v.y - m);

    float p = e0 + e1;
#pragma unroll
    for (int off = 16; off > 0; off >>= 1)
        p += __shfl_down_sync(0xffffffffu, p, off);
    if (lane == 0) s_part[wid] = p;
    __syncthreads();
    if (wid == 0) {
        float t = s_part[lane];
#pragma unroll
        for (int off = 16; off > 0; off >>= 1)
            t += __shfl_down_sync(0xffffffffu, t, off);
        if (lane == 0) s_bcast = t;
    }
    __syncthreads();
    const float S = s_bcast;

    float2 w;
    w.x = e0 / S;
    w.y = e1 / S;
    w2[tid] = w;
}

// ---------------------------------------------------------------------------
// Kernel 2: predicated-FADD2 GEMM + threshold.
// 128x128 tile, BK=16, 256 threads, 8x8 microtile as 8m x 4 N-pair accs.
// A tile: bytes [BK][128] (4KB double-buffered). B tile: floats as R6/R7.
// Per warp-k-step: 2 LDS.32 (A bytes) + 2 LDS.128 (B) + 8x(bfe+setp+4 @p FADD2).
// ---------------------------------------------------------------------------
#define BM 128
#define BN 128
#define BK 16
#define LDB (BN + 4)
#define LDAB 128
#define NKT (K_DIM / BK)

typedef unsigned long long u64t;

// One microtile m-row: extract byte SH of abits, one predicate, 4 packed adds.
// Lanes: acc[j] = {C(m, n2j), C(m, n2j+1)} — each output lane is a serial
// ascending-k chain of fl(acc+b), bit-matching the reference FFMA chain.
#define PRED_ROW(accrow, abits, SH)                                        \
    asm("{\n\t"                                                            \
        ".reg .pred p;\n\t"                                                \
        ".reg .b32 t;\n\t"                                                 \
        "bfe.u32 t, %8, " #SH ", 8;\n\t"                                   \
        "setp.ne.b32 p, t, 0;\n\t"                                         \
        "@p add.rn.f32x2 %0, %0, %4;\n\t"                                  \
        "@p add.rn.f32x2 %1, %1, %5;\n\t"                                  \
        "@p add.rn.f32x2 %2, %2, %6;\n\t"                                  \
        "@p add.rn.f32x2 %3, %3, %7;\n\t"                                  \
        "}"                                                                \
        : "+l"(accrow[0]), "+l"(accrow[1]), "+l"(accrow[2]), "+l"(accrow[3]) \
        : "l"(bq0.x), "l"(bq0.y), "l"(bq1.x), "l"(bq1.y), "r"(abits));

__global__ __launch_bounds__(256, 2) void gemm_thresh_kernel(float* __restrict__ C) {
    const float* __restrict__ B = g_w;
    const unsigned char* __restrict__ Ab_g = g_xbT;

    __shared__ float Bs[2][BK][LDB];
    __shared__ unsigned char Ab[2][BK][LDAB];

    const int tid = threadIdx.x;
    const int bm = blockIdx.y * BM;
    const int bn = blockIdx.x * BN;

    // B loader: 512 float4/tile -> 2 per thread (transposed scalar stores).
    const int lrow0 = tid >> 2;        // 0..63
    const int lrow1 = lrow0 + 64;      // 64..127
    const int lcol = (tid & 3) * 4;    // 0,4,8,12
    // A byte loader: 2KB/tile -> 8 bytes per thread.
    const int arow = tid >> 4;         // 0..15 (k)
    const int acol = (tid & 15) * 8;   // 0..120 (m)

    const int ty = tid >> 4;  // 0..15 (M)
    const int tx = tid & 15;  // 0..15 (N)

    // acc2[i][j]: lanes = (C(m_i, n_{2j}), C(m_i, n_{2j+1}))
    u64t acc2[8][4];
#pragma unroll
    for (int i = 0; i < 8; ++i)
#pragma unroll
        for (int j = 0; j < 4; ++j) acc2[i][j] = 0ull;

    const float* __restrict__ Bp0 = B + (size_t)(bn + lrow0) * K_DIM + lcol;
    const float* __restrict__ Bp1 = B + (size_t)(bn + lrow1) * K_DIM + lcol;
    const unsigned char* __restrict__ Apb = Ab_g + (size_t)arow * M_DIM + bm + acol;

    float4 pb0 = *(const float4*)(Bp0);
    float4 pb1 = *(const float4*)(Bp1);
    u64t pa = *(const u64t*)(Apb);

    int buf = 0;
    Bs[0][lcol + 0][lrow0] = pb0.x; Bs[0][lcol + 1][lrow0] = pb0.y;
    Bs[0][lcol + 2][lrow0] = pb0.z; Bs[0][lcol + 3][lrow0] = pb0.w;
    Bs[0][lcol + 0][lrow1] = pb1.x; Bs[0][lcol + 1][lrow1] = pb1.y;
    Bs[0][lcol + 2][lrow1] = pb1.z; Bs[0][lcol + 3][lrow1] = pb1.w;
    *(u64t*)&Ab[0][arow][acol] = pa;
    __syncthreads();

    for (int kt = 0; kt < NKT; ++kt) {
        const int ko = (kt + 1) * BK;
        const bool has_next = (kt + 1 < NKT);
        if (has_next) {
            pb0 = *(const float4*)(Bp0 + ko);
            pb1 = *(const float4*)(Bp1 + ko);
            pa = *(const u64t*)(Apb + (size_t)ko * M_DIM);
        }

#pragma unroll
        for (int k = 0; k < BK; ++k) {  // k strictly ascending: serial chains
            const unsigned int a0 = *(const unsigned int*)&Ab[buf][k][ty * 4];
            const unsigned int a1 = *(const unsigned int*)&Ab[buf][k][64 + ty * 4];
            const ulonglong2 bq0 = *(const ulonglong2*)&Bs[buf][k][tx * 4];
            const ulonglong2 bq1 = *(const ulonglong2*)&Bs[buf][k][64 + tx * 4];
            PRED_ROW(acc2[0], a0, 0)
            PRED_ROW(acc2[1], a0, 8)
            PRED_ROW(acc2[2], a0, 16)
            PRED_ROW(acc2[3], a0, 24)
            PRED_ROW(acc2[4], a1, 0)
            PRED_ROW(acc2[5], a1, 8)
            PRED_ROW(acc2[6], a1, 16)
            PRED_ROW(acc2[7], a1, 24)
        }

        if (has_next) {
            buf ^= 1;
            Bs[buf][lcol + 0][lrow0] = pb0.x; Bs[buf][lcol + 1][lrow0] = pb0.y;
            Bs[buf][lcol + 2][lrow0] = pb0.z; Bs[buf][lcol + 3][lrow0] = pb0.w;
            Bs[buf][lcol + 0][lrow1] = pb1.x; Bs[buf][lcol + 1][lrow1] = pb1.y;
            Bs[buf][lcol + 2][lrow1] = pb1.z; Bs[buf][lcol + 3][lrow1] = pb1.w;
            *(u64t*)&Ab[buf][arow][acol] = pa;
            __syncthreads();
        }
    }

    // Epilogue: unpack N-pairs, threshold at 0.5, float4 stores.
#pragma unroll
    for (int i = 0; i < 8; ++i) {
        const int m = bm + ((i < 4) ? (ty * 4 + i) : (64 + ty * 4 + (i - 4)));
        float c[8];
#pragma unroll
        for (int j = 0; j < 4; ++j) {
            float lo, hi;
            asm("mov.b64 {%0, %1}, %2;" : "=f"(lo), "=f"(hi) : "l"(acc2[i][j]));
            c[2 * j] = lo;
            c[2 * j + 1] = hi;
        }
        float4 o0, o1;
        o0.x = c[0] > 0.5f ? 1.f : 0.f;
        o0.y = c[1] > 0.5f ? 1.f : 0.f;
        o0.z = c[2] > 0.5f ? 1.f : 0.f;
        o0.w = c[3] > 0.5f ? 1.f : 0.f;
        o1.x = c[4] > 0.5f ? 1.f : 0.f;
        o1.y = c[5] > 0.5f ? 1.f : 0.f;
        o1.z = c[6] > 0.5f ? 1.f : 0.f;
        o1.w = c[7] > 0.5f ? 1.f : 0.f;
        *(float4*)&C[(size_t)m * N_DIM + bn + tx * 4] = o0;
        *(float4*)&C[(size_t)m * N_DIM + bn + 64 + tx * 4] = o1;
    }
}

// ---------------------------------------------------------------------------
extern "C" void kernel_launch(void* const* d_in, const int* in_sizes, int n_in,
                              void* d_out, int out_size) {
    const float* x = (const float*)d_in[0];      // [4096, 2048]
    const float* raw_w = (const float*)d_in[1];  // [2048, 2048]
    float* out = (float*)d_out;                  // [4096, 2048]

    dim3 tgrid(K_DIM / 32, M_DIM / 128);  // (64, 32)
    transpose_x_kernel<<<tgrid, 256>>>(x);

    softmax_rows_kernel<<<N_DIM, 1024>>>(raw_w);

    dim3 grid(N_DIM / BN, M_DIM / BM);  // (16, 32)
    gemm_thresh_kernel<<<grid, 256>>>(out);
}

// round 9
// speedup vs baseline: 1.7749x; 1.7749x over previous
#include <cuda_runtime.h>

// out[b,o] = ( x @ softmax(W,axis=1)^T > 0.5 )
// BIT-REPLICATION constraints (verified: 1 flip @ rel_err 4.888245e-4):
//  - softmax: XLA row-reduction tree replica (kernel 1, DO NOT REORDER)
//  - GEMM: per-output serial ascending-k fp32 fma.rn chain. FFMA2 lanes are
//    independent IEEE fma.rn -> diagonal lane pairing preserves chains.
// R9: 512 threads/CTA, 8x4 microtile, launch_bounds(512,2) -> 32 warps/SM
// (8/SMSP, was 4). A-fragment LDS.128 are warp-uniform broadcasts.

#define M_DIM 4096
#define N_DIM 2048
#define K_DIM 2048

__device__ float g_w[(size_t)N_DIM * K_DIM];

// ---------------------------------------------------------------------------
// Kernel 1: XLA softmax replica (unchanged — bit-exact anchor).
// ---------------------------------------------------------------------------
__global__ __launch_bounds__(1024) void softmax_rows_kernel(const float* __restrict__ raw) {
    const int row = blockIdx.x;
    const int tid = threadIdx.x;
    const int lane = tid & 31;
    const int wid = tid >> 5;

    const float2* __restrict__ r2 =
        reinterpret_cast<const float2*>(raw + (size_t)row * K_DIM);
    float2* __restrict__ w2 = reinterpret_cast<float2*>(g_w + (size_t)row * K_DIM);

    const float2 v = r2[tid];

    __shared__ float s_part[32];
    __shared__ float s_bcast;

    float m = fmaxf(v.x, v.y);
#pragma unroll
    for (int off = 16; off > 0; off >>= 1)
        m = fmaxf(m, __shfl_down_sync(0xffffffffu, m, off));
    if (lane == 0) s_part[wid] = m;
    __syncthreads();
    if (wid == 0) {
        float t = s_part[lane];
#pragma unroll
        for (int off = 16; off > 0; off >>= 1)
            t = fmaxf(t, __shfl_down_sync(0xffffffffu, t, off));
        if (lane == 0) s_bcast = t;
    }
    __syncthreads();
    m = s_bcast;
    __syncthreads();

    const float e0 = expf(v.x - m);
    const float e1 = expf(v.y - m);

    float p = e0 + e1;
#pragma unroll
    for (int off = 16; off > 0; off >>= 1)
        p += __shfl_down_sync(0xffffffffu, p, off);
    if (lane == 0) s_part[wid] = p;
    __syncthreads();
    if (wid == 0) {
        float t = s_part[lane];
#pragma unroll
        for (int off = 16; off > 0; off >>= 1)
            t += __shfl_down_sync(0xffffffffu, t, off);
        if (lane == 0) s_bcast = t;
    }
    __syncthreads();
    const float S = s_bcast;

    float2 w;
    w.x = e0 / S;
    w.y = e1 / S;
    w2[tid] = w;
}

// ---------------------------------------------------------------------------
// Kernel 2: FFMA2 GEMM + threshold, diagonal pairing, 512 threads.
// 128x128 tile, BK=16. Microtile 8M x 4N per thread:
//   M rows: ty*4..+3 and 64+ty*4..+3 (ty = tid>>5, warp-uniform -> LDS bcast)
//   N cols: tx*4..+3 (tx = tid&31)
// Per 2x2 block: diag acc {C(m0,n0),C(m1,n1)}, anti-diag {C(m0,n1),C(m1,n0)}.
// ---------------------------------------------------------------------------
#define BM 128
#define BN 128
#define BK 16
#define LDA (BM + 4)
#define NKT (K_DIM / BK)

typedef unsigned long long u64t;

__device__ __forceinline__ u64t swap_f32x2(u64t v) {
    u64t r;
    asm("{\n\t.reg .b32 lo, hi;\n\t"
        "mov.b64 {lo, hi}, %1;\n\t"
        "mov.b64 %0, {hi, lo};\n\t}"
        : "=l"(r) : "l"(v));
    return r;
}

#define FMA2(acc, a, b) \
    asm("fma.rn.f32x2 %0, %1, %2, %0;" : "+l"(acc) : "l"(a), "l"(b))

__global__ __launch_bounds__(512, 2) void gemm_thresh_kernel(const float* __restrict__ A,
                                                             float* __restrict__ C) {
    const float* __restrict__ B = g_w;

    __shared__ float As[2][BK][LDA];
    __shared__ float Bs[2][BK][LDA];

    const int tid = threadIdx.x;
    const int bm = blockIdx.y * BM;
    const int bn = blockIdx.x * BN;

    // Loaders: tile 128x16 floats = 512 float4 -> 1 per thread, each operand.
    const int lrow = tid >> 2;         // 0..127
    const int lcol = (tid & 3) * 4;    // 0,4,8,12

    const int ty = tid >> 5;  // 0..15 (M), warp-uniform
    const int tx = tid & 31;  // 0..31 (N)

    // acc_d[mp][np].lo = C(m0,n0), .hi = C(m1,n1)
    // acc_a[mp][np].lo = C(m0,n1), .hi = C(m1,n0)
    u64t acc_d[4][2], acc_a[4][2];
#pragma unroll
    for (int i = 0; i < 4; ++i)
#pragma unroll
        for (int j = 0; j < 2; ++j) { acc_d[i][j] = 0ull; acc_a[i][j] = 0ull; }

    const float* __restrict__ Ap = A + (size_t)(bm + lrow) * K_DIM + lcol;
    const float* __restrict__ Bp = B + (size_t)(bn + lrow) * K_DIM + lcol;

    float4 pa = *(const float4*)(Ap);
    float4 pb = *(const float4*)(Bp);

    int buf = 0;
    As[0][lcol + 0][lrow] = pa.x; As[0][lcol + 1][lrow] = pa.y;
    As[0][lcol + 2][lrow] = pa.z; As[0][lcol + 3][lrow] = pa.w;
    Bs[0][lcol + 0][lrow] = pb.x; Bs[0][lcol + 1][lrow] = pb.y;
    Bs[0][lcol + 2][lrow] = pb.z; Bs[0][lcol + 3][lrow] = pb.w;
    __syncthreads();

    for (int kt = 0; kt < NKT; ++kt) {
        const int ko = (kt + 1) * BK;
        const bool has_next = (kt + 1 < NKT);
        if (has_next) {
            pa = *(const float4*)(Ap + ko);
            pb = *(const float4*)(Bp + ko);
        }

#pragma unroll
        for (int k = 0; k < BK; ++k) {  // k strictly ascending: serial chains
            // A: warp-uniform broadcast LDS.128 (m-pairs as 64-bit halves)
            const ulonglong2 aq0 = *(const ulonglong2*)&As[buf][k][ty * 4];
            const ulonglong2 aq1 = *(const ulonglong2*)&As[buf][k][64 + ty * 4];
            // B: one LDS.128 -> two N-pairs
            const ulonglong2 bq = *(const ulonglong2*)&Bs[buf][k][tx * 4];
            const u64t av[4] = {aq0.x, aq0.y, aq1.x, aq1.y};
            const u64t bv[2] = {bq.x, bq.y};
            const u64t bw[2] = {swap_f32x2(bq.x), swap_f32x2(bq.y)};
#pragma unroll
            for (int i = 0; i < 4; ++i) {
#pragma unroll
                for (int j = 0; j < 2; ++j) {
                    FMA2(acc_d[i][j], av[i], bv[j]);
                    FMA2(acc_a[i][j], av[i], bw[j]);
                }
            }
        }

        if (has_next) {
            buf ^= 1;
            As[buf][lcol + 0][lrow] = pa.x; As[buf][lcol + 1][lrow] = pa.y;
            As[buf][lcol + 2][lrow] = pa.z; As[buf][lcol + 3][lrow] = pa.w;
            Bs[buf][lcol + 0][lrow] = pb.x; Bs[buf][lcol + 1][lrow] = pb.y;
            Bs[buf][lcol + 2][lrow] = pb.z; Bs[buf][lcol + 3][lrow] = pb.w;
            __syncthreads();
        }
    }

    // Epilogue: decode diag/anti-diag lanes, threshold, float4 stores.
#pragma unroll
    for (int mp = 0; mp < 4; ++mp) {
        const int r0 = bm + ((mp < 2) ? ty * 4 : 64 + ty * 4) + (mp & 1) * 2;
        const int r1 = r0 + 1;

        float dlo[2], dhi[2], alo[2], ahi[2];
#pragma unroll
        for (int j = 0; j < 2; ++j) {
            asm("mov.b64 {%0, %1}, %2;" : "=f"(dlo[j]), "=f"(dhi[j]) : "l"(acc_d[mp][j]));
            asm("mov.b64 {%0, %1}, %2;" : "=f"(alo[j]), "=f"(ahi[j]) : "l"(acc_a[mp][j]));
        }

        float4 o;
        // row r0: cols tx*4 .. +3 = [d0.lo, a0.lo, d1.lo, a1.lo]
        o.x = dlo[0] > 0.5f ? 1.f : 0.f;
        o.y = alo[0] > 0.5f ? 1.f : 0.f;
        o.z = dlo[1] > 0.5f ? 1.f : 0.f;
        o.w = alo[1] > 0.5f ? 1.f : 0.f;
        *(float4*)&C[(size_t)r0 * N_DIM + bn + tx * 4] = o;
        // row r1: [a0.hi, d0.hi, a1.hi, d1.hi]
        o.x = ahi[0] > 0.5f ? 1.f : 0.f;
        o.y = dhi[0] > 0.5f ? 1.f : 0.f;
        o.z = ahi[1] > 0.5f ? 1.f : 0.f;
        o.w = dhi[1] > 0.5f ? 1.f : 0.f;
        *(float4*)&C[(size_t)r1 * N_DIM + bn + tx * 4] = o;
    }
}

// ---------------------------------------------------------------------------
extern "C" void kernel_launch(void* const* d_in, const int* in_sizes, int n_in,
                              void* d_out, int out_size) {
    const float* x = (const float*)d_in[0];      // [4096, 2048]
    const float* raw_w = (const float*)d_in[1];  // [2048, 2048]
    float* out = (float*)d_out;                  // [4096, 2048]

    softmax_rows_kernel<<<N_DIM, 1024>>>(raw_w);

    dim3 grid(N_DIM / BN, M_DIM / BM);  // (16, 32)
    gemm_thresh_kernel<<<grid, 512>>>(x, out);
}

// round 10
// speedup vs baseline: 2.0338x; 1.1459x over previous
#include <cuda_runtime.h>

// out[b,o] = ( x @ softmax(W,axis=1)^T > 0.5 )
// BIT-REPLICATION constraints (verified: 1 flip @ rel_err 4.888245e-4):
//  - softmax: XLA row-reduction tree replica (kernel 1, DO NOT REORDER)
//  - GEMM: per-output serial ascending-k fp32 fma.rn chain. FFMA2 lanes are
//    independent IEEE fma.rn -> diagonal lane pairing preserves chains.
// R10: 256 threads, warp-wide N (1 LDS.128 B) + 16-row M-strip via 4
// BROADCAST LDS.128 -> 8 crossbar-cyc per 64 fma-pipe-cyc: fma-pipe-bound.

#define M_DIM 4096
#define N_DIM 2048
#define K_DIM 2048

__device__ float g_w[(size_t)N_DIM * K_DIM];

// ---------------------------------------------------------------------------
// Kernel 1: XLA softmax replica (unchanged — bit-exact anchor).
// ---------------------------------------------------------------------------
__global__ __launch_bounds__(1024) void softmax_rows_kernel(const float* __restrict__ raw) {
    const int row = blockIdx.x;
    const int tid = threadIdx.x;
    const int lane = tid & 31;
    const int wid = tid >> 5;

    const float2* __restrict__ r2 =
        reinterpret_cast<const float2*>(raw + (size_t)row * K_DIM);
    float2* __restrict__ w2 = reinterpret_cast<float2*>(g_w + (size_t)row * K_DIM);

    const float2 v = r2[tid];

    __shared__ float s_part[32];
    __shared__ float s_bcast;

    float m = fmaxf(v.x, v.y);
#pragma unroll
    for (int off = 16; off > 0; off >>= 1)
        m = fmaxf(m, __shfl_down_sync(0xffffffffu, m, off));
    if (lane == 0) s_part[wid] = m;
    __syncthreads();
    if (wid == 0) {
        float t = s_part[lane];
#pragma unroll
        for (int off = 16; off > 0; off >>= 1)
            t = fmaxf(t, __shfl_down_sync(0xffffffffu, t, off));
        if (lane == 0) s_bcast = t;
    }
    __syncthreads();
    m = s_bcast;
    __syncthreads();

    const float e0 = expf(v.x - m);
    const float e1 = expf(v.y - m);

    float p = e0 + e1;
#pragma unroll
    for (int off = 16; off > 0; off >>= 1)
        p += __shfl_down_sync(0xffffffffu, p, off);
    if (lane == 0) s_part[wid] = p;
    __syncthreads();
    if (wid == 0) {
        float t = s_part[lane];
#pragma unroll
        for (int off = 16; off > 0; off >>= 1)
            t += __shfl_down_sync(0xffffffffu, t, off);
        if (lane == 0) s_bcast = t;
    }
    __syncthreads();
    const float S = s_bcast;

    float2 w;
    w.x = e0 / S;
    w.y = e1 / S;
    w2[tid] = w;
}

// ---------------------------------------------------------------------------
// Kernel 2: FFMA2 GEMM + threshold, diagonal pairing.
// 128x128 tile, BK=16, 256 threads (8 warps).
//   Warp w owns M rows [w*16, w*16+16): A frag = 4 broadcast LDS.128.
//   Lane l owns N cols [l*4, l*4+4):   B frag = 1 LDS.128.
// Microtile 16M x 4N = 8 M-pairs x 2 N-pairs, diag+anti-diag FFMA2 (32/k).
// ---------------------------------------------------------------------------
#define BM 128
#define BN 128
#define BK 16
#define LDA (BM + 4)
#define NKT (K_DIM / BK)

typedef unsigned long long u64t;

__device__ __forceinline__ u64t swap_f32x2(u64t v) {
    u64t r;
    asm("{\n\t.reg .b32 lo, hi;\n\t"
        "mov.b64 {lo, hi}, %1;\n\t"
        "mov.b64 %0, {hi, lo};\n\t}"
        : "=l"(r) : "l"(v));
    return r;
}

#define FMA2(acc, a, b) \
    asm("fma.rn.f32x2 %0, %1, %2, %0;" : "+l"(acc) : "l"(a), "l"(b))

__global__ __launch_bounds__(256, 2) void gemm_thresh_kernel(const float* __restrict__ A,
                                                             float* __restrict__ C) {
    const float* __restrict__ B = g_w;

    __shared__ float As[2][BK][LDA];
    __shared__ float Bs[2][BK][LDA];

    const int tid = threadIdx.x;
    const int bm = blockIdx.y * BM;
    const int bn = blockIdx.x * BN;

    // Loaders: 512 float4 per operand tile -> 2 per thread each.
    const int lrow0 = tid >> 2;        // 0..63
    const int lrow1 = lrow0 + 64;      // 64..127
    const int lcol = (tid & 3) * 4;    // 0,4,8,12

    const int ty = tid >> 5;  // warp id 0..7 -> M strip [ty*16, ty*16+16)
    const int tx = tid & 31;  // lane -> N cols [tx*4, tx*4+4)

    // acc_d[mp][np].lo = C(m0,n0), .hi = C(m1,n1)
    // acc_a[mp][np].lo = C(m0,n1), .hi = C(m1,n0)
    //   m0 = bm + ty*16 + mp*2, m1 = m0+1 ; n0 = bn + tx*4 + np*2, n1 = n0+1
    u64t acc_d[8][2], acc_a[8][2];
#pragma unroll
    for (int i = 0; i < 8; ++i)
#pragma unroll
        for (int j = 0; j < 2; ++j) { acc_d[i][j] = 0ull; acc_a[i][j] = 0ull; }

    const float* __restrict__ Ap0 = A + (size_t)(bm + lrow0) * K_DIM + lcol;
    const float* __restrict__ Ap1 = A + (size_t)(bm + lrow1) * K_DIM + lcol;
    const float* __restrict__ Bp0 = B + (size_t)(bn + lrow0) * K_DIM + lcol;
    const float* __restrict__ Bp1 = B + (size_t)(bn + lrow1) * K_DIM + lcol;

    float4 pa0 = *(const float4*)(Ap0);
    float4 pa1 = *(const float4*)(Ap1);
    float4 pb0 = *(const float4*)(Bp0);
    float4 pb1 = *(const float4*)(Bp1);

    int buf = 0;
    As[0][lcol + 0][lrow0] = pa0.x; As[0][lcol + 1][lrow0] = pa0.y;
    As[0][lcol + 2][lrow0] = pa0.z; As[0][lcol + 3][lrow0] = pa0.w;
    As[0][lcol + 0][lrow1] = pa1.x; As[0][lcol + 1][lrow1] = pa1.y;
    As[0][lcol + 2][lrow1] = pa1.z; As[0][lcol + 3][lrow1] = pa1.w;
    Bs[0][lcol + 0][lrow0] = pb0.x; Bs[0][lcol + 1][lrow0] = pb0.y;
    Bs[0][lcol + 2][lrow0] = pb0.z; Bs[0][lcol + 3][lrow0] = pb0.w;
    Bs[0][lcol + 0][lrow1] = pb1.x; Bs[0][lcol + 1][lrow1] = pb1.y;
    Bs[0][lcol + 2][lrow1] = pb1.z; Bs[0][lcol + 3][lrow1] = pb1.w;
    __syncthreads();

    for (int kt = 0; kt < NKT; ++kt) {
        const int ko = (kt + 1) * BK;
        const bool has_next = (kt + 1 < NKT);
        if (has_next) {
            pa0 = *(const float4*)(Ap0 + ko);
            pa1 = *(const float4*)(Ap1 + ko);
            pb0 = *(const float4*)(Bp0 + ko);
            pb1 = *(const float4*)(Bp1 + ko);
        }

#pragma unroll
        for (int k = 0; k < BK; ++k) {  // k strictly ascending: serial chains
            // A strip: 4 broadcast LDS.128 -> 8 m-pair u64 halves
            const ulonglong2 aq0 = *(const ulonglong2*)&As[buf][k][ty * 16];
            const ulonglong2 aq1 = *(const ulonglong2*)&As[buf][k][ty * 16 + 4];
            const ulonglong2 aq2 = *(const ulonglong2*)&As[buf][k][ty * 16 + 8];
            const ulonglong2 aq3 = *(const ulonglong2*)&As[buf][k][ty * 16 + 12];
            // B: one LDS.128 -> two N-pairs + swapped copies
            const ulonglong2 bq = *(const ulonglong2*)&Bs[buf][k][tx * 4];
            const u64t av[8] = {aq0.x, aq0.y, aq1.x, aq1.y,
                                aq2.x, aq2.y, aq3.x, aq3.y};
            const u64t bv[2] = {bq.x, bq.y};
            const u64t bw[2] = {swap_f32x2(bq.x), swap_f32x2(bq.y)};
#pragma unroll
            for (int i = 0; i < 8; ++i) {
#pragma unroll
                for (int j = 0; j < 2; ++j) {
                    FMA2(acc_d[i][j], av[i], bv[j]);
                    FMA2(acc_a[i][j], av[i], bw[j]);
                }
            }
        }

        if (has_next) {
            buf ^= 1;
            As[buf][lcol + 0][lrow0] = pa0.x; As[buf][lcol + 1][lrow0] = pa0.y;
            As[buf][lcol + 2][lrow0] = pa0.z; As[buf][lcol + 3][lrow0] = pa0.w;
            As[buf][lcol + 0][lrow1] = pa1.x; As[buf][lcol + 1][lrow1] = pa1.y;
            As[buf][lcol + 2][lrow1] = pa1.z; As[buf][lcol + 3][lrow1] = pa1.w;
            Bs[buf][lcol + 0][lrow0] = pb0.x; Bs[buf][lcol + 1][lrow0] = pb0.y;
            Bs[buf][lcol + 2][lrow0] = pb0.z; Bs[buf][lcol + 3][lrow0] = pb0.w;
            Bs[buf][lcol + 0][lrow1] = pb1.x; Bs[buf][lcol + 1][lrow1] = pb1.y;
            Bs[buf][lcol + 2][lrow1] = pb1.z; Bs[buf][lcol + 3][lrow1] = pb1.w;
            __syncthreads();
        }
    }

    // Epilogue: decode diag/anti-diag lanes, threshold, float4 stores.
#pragma unroll
    for (int mp = 0; mp < 8; ++mp) {
        const int r0 = bm + ty * 16 + mp * 2;
        const int r1 = r0 + 1;

        float dlo[2], dhi[2], alo[2], ahi[2];
#pragma unroll
        for (int j = 0; j < 2; ++j) {
            asm("mov.b64 {%0, %1}, %2;" : "=f"(dlo[j]), "=f"(dhi[j]) : "l"(acc_d[mp][j]));
            asm("mov.b64 {%0, %1}, %2;" : "=f"(alo[j]), "=f"(ahi[j]) : "l"(acc_a[mp][j]));
        }

        float4 o;
        // row r0: cols tx*4 .. +3 = [d0.lo, a0.lo, d1.lo, a1.lo]
        o.x = dlo[0] > 0.5f ? 1.f : 0.f;
        o.y = alo[0] > 0.5f ? 1.f : 0.f;
        o.z = dlo[1] > 0.5f ? 1.f : 0.f;
        o.w = alo[1] > 0.5f ? 1.f : 0.f;
        *(float4*)&C[(size_t)r0 * N_DIM + bn + tx * 4] = o;
        // row r1: [a0.hi, d0.hi, a1.hi, d1.hi]
        o.x = ahi[0] > 0.5f ? 1.f : 0.f;
        o.y = dhi[0] > 0.5f ? 1.f : 0.f;
        o.z = ahi[1] > 0.5f ? 1.f : 0.f;
        o.w = dhi[1] > 0.5f ? 1.f : 0.f;
        *(float4*)&C[(size_t)r1 * N_DIM + bn + tx * 4] = o;
    }
}

// ---------------------------------------------------------------------------
extern "C" void kernel_launch(void* const* d_in, const int* in_sizes, int n_in,
                              void* d_out, int out_size) {
    const float* x = (const float*)d_in[0];      // [4096, 2048]
    const float* raw_w = (const float*)d_in[1];  // [2048, 2048]
    float* out = (float*)d_out;                  // [4096, 2048]

    softmax_rows_kernel<<<N_DIM, 1024>>>(raw_w);

    dim3 grid(N_DIM / BN, M_DIM / BM);  // (16, 32)
    gemm_thresh_kernel<<<grid, 256>>>(x, out);
}